// round 13
// baseline (speedup 1.0000x reference)
#include <cuda_runtime.h>
#include <cuda_bf16.h>
#include <math.h>
#include <stdint.h>

// Problem constants
#define V_    50000
#define IN_   300
#define M_    150
#define G3_   450      // 3*M
#define NL_   200000
#define D_    6
#define N_    40000
#define K_    4
#define B_    64
#define S_    64
#define NCTX  (B_*S_)          // 4096
#define NJOB  (NCTX*5)         // 20480

// GEMM tiling (fragment-order operands)
#define NP    480              // n padded to 60*8
#define NT    60               // n8 tiles
#define NTG   15               // n8 tiles per warp
#define KCH   19               // k16 chunks; k indices up to 303 -> zero-guarded vs IN_=300
#define NMT   (NJOB/16)        // 1280 m16 tiles
#define SAC   488              // smem acc row stride (floats), bank-staggered
#define SMEM_GEMM (32 * SAC * 4)   // 62464 B dynamic smem

// dep kernel tiling (unchanged from R8)
#define TC 8
#define PC (TC/2)
#define SDP 4
#define SHT 4

// Scratch (device globals — no allocation allowed)
__device__ int   g_job[NJOB];
__device__ int   g_type[NCTX];
__device__ int   g_word[NCTX];
__device__ float g_c[(size_t)NJOB * M_];
__device__ float g_h[(size_t)NJOB * M_];
__device__ uint4 g_Afh[(size_t)NMT * KCH * 32];    // A fragments, hi plane
__device__ uint4 g_Afl[(size_t)NMT * KCH * 32];    // A fragments, lo plane
__device__ uint2 g_Wfh[(size_t)KCH * NT * 32];     // B fragments, hi plane
__device__ uint2 g_Wfl[(size_t)KCH * NT * 32];     // B fragments, lo plane

__device__ __forceinline__ float sigm(float x) { return 1.0f / (1.0f + expf(-x)); }

__device__ __forceinline__ unsigned long long pack2(float lo, float hi) {
    unsigned long long r;
    asm("mov.b64 %0, {%1, %2};" : "=l"(r) : "f"(lo), "f"(hi));
    return r;
}
__device__ __forceinline__ void unpack2(unsigned long long v, float& lo, float& hi) {
    asm("mov.b64 {%0, %1}, %2;" : "=f"(lo), "=f"(hi) : "l"(v));
}
__device__ __forceinline__ unsigned long long fma2(unsigned long long a,
                                                   unsigned long long b,
                                                   unsigned long long c) {
    unsigned long long d;
    asm("fma.rn.f32x2 %0, %1, %2, %3;" : "=l"(d) : "l"(a), "l"(b), "l"(c));
    return d;
}
__device__ __forceinline__ unsigned long long add2(unsigned long long a,
                                                   unsigned long long b) {
    unsigned long long d;
    asm("add.rn.f32x2 %0, %1, %2;" : "=l"(d) : "l"(a), "l"(b));
    return d;
}

__device__ __forceinline__ uint32_t pack_bf2(float x0, float x1) {
    __nv_bfloat162 v = __floats2bfloat162_rn(x0, x1);
    return *reinterpret_cast<uint32_t*>(&v);
}
__device__ __forceinline__ void split2(float x, float& hi, float& lo) {
    __nv_bfloat16 h = __float2bfloat16(x);
    hi = __bfloat162float(h);
    lo = x - hi;
}

// ---------------------------------------------------------------------------
// Kernel A: classify each ctx element, build the leaf-job list
// ---------------------------------------------------------------------------
__global__ void build_jobs_kernel(const int* __restrict__ ctx,
                                  const int* __restrict__ dep_word,
                                  const int* __restrict__ dep_child) {
    int e = blockIdx.x * blockDim.x + threadIdx.x;
    if (e >= NCTX) return;
    int s = ctx[e];
    int base = e * 5;
    int j[5] = {-1, -1, -1, -1, -1};
    int type = 0, word = 0;
    if (s == 0) {
        type = 0;
    } else if (s <= NL_) {
        type = 1;
        j[0] = s - 1;
    } else {
        type = 2;
        int node = s - 1 - NL_;
        word = dep_word[node];
        #pragma unroll
        for (int k = 0; k < K_; k++) {
            int cs = dep_child[node * K_ + k];
            j[1 + k] = (cs >= 1 && cs <= NL_) ? (cs - 1) : -1;
        }
    }
    #pragma unroll
    for (int q = 0; q < 5; q++) g_job[base + q] = j[q];
    g_type[e] = type;
    g_word[e] = word;
}

// ---------------------------------------------------------------------------
// prep_w_frag: W_leaf -> mma B fragments (hi/lo), fragment-order layout.
// ---------------------------------------------------------------------------
__global__ void prep_w_frag_kernel(const float* __restrict__ Wl) {
    int idx = blockIdx.x * blockDim.x + threadIdx.x;   // over KCH*NT*32
    if (idx >= KCH * NT * 32) return;
    int kc   = idx / (NT * 32);
    int r    = idx - kc * (NT * 32);
    int nt   = r >> 5;
    int lane = r & 31;
    int gid  = lane >> 2;
    int tig  = lane & 3;
    int n  = nt * 8 + gid;
    int k0 = kc * 16 + 2 * tig;
    float w00 = 0.f, w01 = 0.f, w10 = 0.f, w11 = 0.f;
    if (n < G3_) {
        if (k0     < IN_) w00 = Wl[(size_t)k0 * G3_ + n];
        if (k0 + 1 < IN_) w01 = Wl[(size_t)(k0 + 1) * G3_ + n];
        if (k0 + 8 < IN_) w10 = Wl[(size_t)(k0 + 8) * G3_ + n];
        if (k0 + 9 < IN_) w11 = Wl[(size_t)(k0 + 9) * G3_ + n];
    }
    float h00, l00, h01, l01, h10, l10, h11, l11;
    split2(w00, h00, l00); split2(w01, h01, l01);
    split2(w10, h10, l10); split2(w11, h11, l11);
    g_Wfh[idx] = make_uint2(pack_bf2(h00, h01), pack_bf2(h10, h11));
    g_Wfl[idx] = make_uint2(pack_bf2(l00, l01), pack_bf2(l10, l11));
}

// ---------------------------------------------------------------------------
// prep_x_frag: gathered embeddings -> mma A fragments (hi/lo).
// ---------------------------------------------------------------------------
__global__ void prep_x_frag_kernel(const float* __restrict__ embed,
                                   const int*   __restrict__ leaf_idx) {
    int idx = blockIdx.x * blockDim.x + threadIdx.x;   // over NMT*KCH*32
    if (idx >= NMT * KCH * 32) return;
    int mt   = idx / (KCH * 32);
    int r    = idx - mt * (KCH * 32);
    int kc   = r >> 5;
    int lane = r & 31;
    int gid  = lane >> 2;
    int tig  = lane & 3;
    int j0 = mt * 16 + gid;
    int j1 = j0 + 8;
    int k  = kc * 16 + 2 * tig;

    int jb0 = g_job[j0], jb1 = g_job[j1];
    float x00 = 0.f, x01 = 0.f, x08 = 0.f, x09 = 0.f;
    float y00 = 0.f, y01 = 0.f, y08 = 0.f, y09 = 0.f;
    if (jb0 >= 0) {
        const float* row = embed + (size_t)leaf_idx[jb0] * IN_;
        if (k     < IN_) x00 = row[k];
        if (k + 1 < IN_) x01 = row[k + 1];
        if (k + 8 < IN_) x08 = row[k + 8];
        if (k + 9 < IN_) x09 = row[k + 9];
    }
    if (jb1 >= 0) {
        const float* row = embed + (size_t)leaf_idx[jb1] * IN_;
        if (k     < IN_) y00 = row[k];
        if (k + 1 < IN_) y01 = row[k + 1];
        if (k + 8 < IN_) y08 = row[k + 8];
        if (k + 9 < IN_) y09 = row[k + 9];
    }
    float hx00,lx00,hx01,lx01,hx08,lx08,hx09,lx09;
    float hy00,ly00,hy01,ly01,hy08,ly08,hy09,ly09;
    split2(x00,hx00,lx00); split2(x01,hx01,lx01);
    split2(x08,hx08,lx08); split2(x09,hx09,lx09);
    split2(y00,hy00,ly00); split2(y01,hy01,ly01);
    split2(y08,hy08,ly08); split2(y09,hy09,ly09);
    g_Afh[idx] = make_uint4(pack_bf2(hx00,hx01), pack_bf2(hy00,hy01),
                            pack_bf2(hx08,hx09), pack_bf2(hy08,hy09));
    g_Afl[idx] = make_uint4(pack_bf2(lx00,lx01), pack_bf2(ly00,ly01),
                            pack_bf2(lx08,lx09), pack_bf2(ly08,ly09));
}

// ---------------------------------------------------------------------------
// leaf_gemm: 3-plane bf16 split GEMM, software-pipelined, fused epilogue.
// Block = 128 thr (4 warps) = 2 m-tiles (32 jobs) x 60 n-tiles.
// Warp ng covers n-tiles [ng*15, ng*15+15) for BOTH m-tiles (B reuse x2).
// Grid = NJOB/32 = 640.
// ---------------------------------------------------------------------------
#define MMA_ACC(C, A, Bv)                                                      \
    asm volatile(                                                              \
        "mma.sync.aligned.m16n8k16.row.col.f32.bf16.bf16.f32 "                 \
        "{%0,%1,%2,%3}, {%4,%5,%6,%7}, {%8,%9}, {%0,%1,%2,%3};"                \
        : "+f"((C)[0]), "+f"((C)[1]), "+f"((C)[2]), "+f"((C)[3])               \
        : "r"((A).x), "r"((A).y), "r"((A).z), "r"((A).w),                      \
          "r"((Bv).x), "r"((Bv).y))

__global__ void __launch_bounds__(128, 2)
leaf_gemm_kernel(const float* __restrict__ bl) {
    extern __shared__ float s_acc[];   // [32][SAC]
    const int lane = threadIdx.x & 31;
    const int ng   = threadIdx.x >> 5;     // 0..3
    const int gid  = lane >> 2;
    const int tig  = lane & 3;
    const int mt0  = blockIdx.x * 2;
    const int mt1  = mt0 + 1;
    const int nt0  = ng * NTG;

    float c0[NTG][4], c1[NTG][4];
    #pragma unroll
    for (int t = 0; t < NTG; t++) {
        c0[t][0]=0.f; c0[t][1]=0.f; c0[t][2]=0.f; c0[t][3]=0.f;
        c1[t][0]=0.f; c1[t][1]=0.f; c1[t][2]=0.f; c1[t][3]=0.f;
    }

    const uint4* Ah0 = g_Afh + (size_t)mt0 * KCH * 32 + lane;
    const uint4* Ah1 = g_Afh + (size_t)mt1 * KCH * 32 + lane;
    const uint4* Al0 = g_Afl + (size_t)mt0 * KCH * 32 + lane;
    const uint4* Al1 = g_Afl + (size_t)mt1 * KCH * 32 + lane;

    #define GEMM_PLANE(A0P, A1P, BP) do {                                      \
        uint4 a0c = (A0P)[0];                                                  \
        uint4 a1c = (A1P)[0];                                                  \
        uint2 bc[NTG];                                                         \
        _Pragma("unroll")                                                      \
        for (int t = 0; t < NTG; t++)                                          \
            bc[t] = (BP)[(size_t)(nt0 + t) * 32 + lane];                       \
        _Pragma("unroll")                                                      \
        for (int kc = 0; kc < KCH; kc++) {                                     \
            uint4 a0n, a1n; uint2 bn[NTG];                                     \
            if (kc + 1 < KCH) {                                                \
                a0n = (A0P)[(kc + 1) * 32];                                    \
                a1n = (A1P)[(kc + 1) * 32];                                    \
                _Pragma("unroll")                                              \
                for (int t = 0; t < NTG; t++)                                  \
                    bn[t] = (BP)[((size_t)(kc + 1) * NT + nt0 + t) * 32 + lane];\
            }                                                                  \
            _Pragma("unroll")                                                  \
            for (int t = 0; t < NTG; t++) {                                    \
                MMA_ACC(c0[t], a0c, bc[t]);                                    \
                MMA_ACC(c1[t], a1c, bc[t]);                                    \
            }                                                                  \
            if (kc + 1 < KCH) {                                                \
                a0c = a0n; a1c = a1n;                                          \
                _Pragma("unroll")                                              \
                for (int t = 0; t < NTG; t++) bc[t] = bn[t];                   \
            }                                                                  \
        }                                                                      \
    } while (0)

    GEMM_PLANE(Ah0, Ah1, g_Wfh);   // hi * hi
    GEMM_PLANE(Ah0, Ah1, g_Wfl);   // hi * lo
    GEMM_PLANE(Al0, Al1, g_Wfh);   // lo * hi
    #undef GEMM_PLANE

    // stage accumulators to smem: local rows 0..31 = jobs [blockIdx*32, +32)
    #pragma unroll
    for (int t = 0; t < NTG; t++) {
        int n0 = (nt0 + t) * 8 + 2 * tig;
        *reinterpret_cast<float2*>(&s_acc[(gid     ) * SAC + n0]) = make_float2(c0[t][0], c0[t][1]);
        *reinterpret_cast<float2*>(&s_acc[(gid +  8) * SAC + n0]) = make_float2(c0[t][2], c0[t][3]);
        *reinterpret_cast<float2*>(&s_acc[(gid + 16) * SAC + n0]) = make_float2(c1[t][0], c1[t][1]);
        *reinterpret_cast<float2*>(&s_acc[(gid + 24) * SAC + n0]) = make_float2(c1[t][2], c1[t][3]);
    }
    __syncthreads();

    // fused epilogue: gates for 32 jobs x 150 lanes
    const int jb32 = blockIdx.x * 32;
    for (int idx = threadIdx.x; idx < 32 * M_; idx += 128) {
        int lj = idx / M_;
        int m  = idx - lj * M_;
        int j  = jb32 + lj;
        float cc = 0.f, hh = 0.f;
        if (g_job[j] >= 0) {
            float i_ = sigm(s_acc[lj * SAC + m]           + bl[m]);
            float o_ = sigm(s_acc[lj * SAC + M_ + m]      + bl[M_ + m]);
            float u_ = tanhf(s_acc[lj * SAC + 2 * M_ + m] + bl[2 * M_ + m]);
            cc = i_ * u_;
            hh = o_ * tanhf(cc);
        }
        g_c[(size_t)j * M_ + m] = cc;
        g_h[(size_t)j * M_ + m] = hh;
    }
}

// ---------------------------------------------------------------------------
// Kernel C: dep-node cell (unchanged from R8: pair-packed f32x2, occ 3)
// ---------------------------------------------------------------------------
__global__ void __launch_bounds__(160, 3)
dep_kernel(const float* __restrict__ embed,
           const float* __restrict__ Wiou,
           const float* __restrict__ Uiou,
           const float* __restrict__ biou,
           const float* __restrict__ Wf,
           const float* __restrict__ Uf,
           const float* __restrict__ bf,
           float* __restrict__ out) {
    __shared__ __align__(16) float2 sxd2[IN_ * SDP];
    __shared__ __align__(16) float2 sh2 [K_ * M_ * SHT];
    __shared__ __align__(16) float2 shs2[M_ * SDP];
    __shared__ int styp[TC];
    __shared__ int sword[TC];

    const int eb  = blockIdx.x * TC;
    const int tid = threadIdx.x;

    if (tid < TC) {
        styp[tid]  = g_type[eb + tid];
        sword[tid] = g_word[eb + tid];
    }
    __syncthreads();

    for (int idx = tid; idx < PC * IN_; idx += blockDim.x) {
        int p = idx / IN_;
        int t = idx - p * IN_;
        int l0 = 2 * p, l1 = 2 * p + 1;
        float a = (styp[l0] == 2) ? embed[(size_t)sword[l0] * IN_ + t] : 0.0f;
        float b = (styp[l1] == 2) ? embed[(size_t)sword[l1] * IN_ + t] : 0.0f;
        sxd2[t * SDP + p] = make_float2(a, b);
    }
    for (int idx = tid; idx < PC * K_ * M_; idx += blockDim.x) {
        int pk = idx / M_;
        int t  = idx - pk * M_;
        int p  = pk / K_;
        int k  = pk - p * K_;
        int l0 = 2 * p, l1 = 2 * p + 1;
        float a = (styp[l0] == 2) ? g_h[((size_t)(eb + l0) * 5 + 1 + k) * M_ + t] : 0.0f;
        float b = (styp[l1] == 2) ? g_h[((size_t)(eb + l1) * 5 + 1 + k) * M_ + t] : 0.0f;
        sh2[(k * M_ + t) * SHT + p] = make_float2(a, b);
    }
    __syncthreads();
    for (int idx = tid; idx < PC * M_; idx += blockDim.x) {
        int p = idx / M_;
        int t = idx - p * M_;
        const unsigned long long* s64 =
            reinterpret_cast<const unsigned long long*>(sh2);
        unsigned long long s = add2(add2(s64[(0 * M_ + t) * SHT + p],
                                         s64[(1 * M_ + t) * SHT + p]),
                                    add2(s64[(2 * M_ + t) * SHT + p],
                                         s64[(3 * M_ + t) * SHT + p]));
        reinterpret_cast<unsigned long long*>(shs2)[t * SDP + p] = s;
    }
    __syncthreads();

    if (tid < M_) {
        unsigned long long ai[PC], ao[PC], au[PC], axf[PC], af[PC][K_];
        #pragma unroll
        for (int p = 0; p < PC; p++) {
            ai[p] = 0ull; ao[p] = 0ull; au[p] = 0ull; axf[p] = 0ull;
            #pragma unroll
            for (int k = 0; k < K_; k++) af[p][k] = 0ull;
        }

        #pragma unroll 2
        for (int t = 0; t < IN_; t++) {
            float wi = __ldg(Wiou + (size_t)t * G3_ + tid);
            float wo = __ldg(Wiou + (size_t)t * G3_ + M_ + tid);
            float wu = __ldg(Wiou + (size_t)t * G3_ + 2 * M_ + tid);
            float wf = __ldg(Wf   + (size_t)t * M_ + tid);
            unsigned long long wip = pack2(wi, wi);
            unsigned long long wop = pack2(wo, wo);
            unsigned long long wup = pack2(wu, wu);
            unsigned long long wfp = pack2(wf, wf);
            const ulonglong2* row =
                reinterpret_cast<const ulonglong2*>(sxd2 + t * SDP);
            ulonglong2 x01 = row[0];
            ulonglong2 x23 = row[1];
            unsigned long long xv[PC] = {x01.x, x01.y, x23.x, x23.y};
            #pragma unroll
            for (int p = 0; p < PC; p++) {
                ai[p]  = fma2(xv[p], wip, ai[p]);
                ao[p]  = fma2(xv[p], wop, ao[p]);
                au[p]  = fma2(xv[p], wup, au[p]);
                axf[p] = fma2(xv[p], wfp, axf[p]);
            }
        }
        #pragma unroll 2
        for (int t = 0; t < M_; t++) {
            float ui = __ldg(Uiou + (size_t)t * G3_ + tid);
            float uo = __ldg(Uiou + (size_t)t * G3_ + M_ + tid);
            float uu = __ldg(Uiou + (size_t)t * G3_ + 2 * M_ + tid);
            float uf = __ldg(Uf   + (size_t)t * M_ + tid);
            unsigned long long uip = pack2(ui, ui);
            unsigned long long uop = pack2(uo, uo);
            unsigned long long uup = pack2(uu, uu);
            unsigned long long ufp = pack2(uf, uf);
            const ulonglong2* srow =
                reinterpret_cast<const ulonglong2*>(shs2 + t * SDP);
            ulonglong2 h01 = srow[0];
            ulonglong2 h23 = srow[1];
            unsigned long long hv[PC] = {h01.x, h01.y, h23.x, h23.y};
            #pragma unroll
            for (int p = 0; p < PC; p++) {
                ai[p] = fma2(hv[p], uip, ai[p]);
                ao[p] = fma2(hv[p], uop, ao[p]);
                au[p] = fma2(hv[p], uup, au[p]);
            }
            #pragma unroll
            for (int k = 0; k < K_; k++) {
                const ulonglong2* krow =
                    reinterpret_cast<const ulonglong2*>(sh2 + (k * M_ + t) * SHT);
                ulonglong2 k01 = krow[0];
                ulonglong2 k23 = krow[1];
                unsigned long long kv[PC] = {k01.x, k01.y, k23.x, k23.y};
                #pragma unroll
                for (int p = 0; p < PC; p++)
                    af[p][k] = fma2(kv[p], ufp, af[p][k]);
            }
        }

        const float bi = biou[tid], bo = biou[M_ + tid], bu = biou[2 * M_ + tid];
        const float bff = bf[tid];
        #pragma unroll
        for (int p = 0; p < PC; p++) {
            float i0, i1, o0, o1, u0, u1, x0, x1;
            unpack2(ai[p], i0, i1);
            unpack2(ao[p], o0, o1);
            unpack2(au[p], u0, u1);
            unpack2(axf[p], x0, x1);
            float f0[K_], f1[K_];
            #pragma unroll
            for (int k = 0; k < K_; k++) unpack2(af[p][k], f0[k], f1[k]);
            #pragma unroll
            for (int half = 0; half < 2; half++) {
                int l = 2 * p + half;
                if (styp[l] != 2) continue;
                int e = eb + l;
                float i_ = sigm((half ? i1 : i0) + bi);
                float o_ = sigm((half ? o1 : o0) + bo);
                float u_ = tanhf((half ? u1 : u0) + bu);
                float xf = half ? x1 : x0;
                float c  = i_ * u_;
                #pragma unroll
                for (int k = 0; k < K_; k++) {
                    float f  = sigm(xf + (half ? f1[k] : f0[k]) + bff);
                    float cc = g_c[((size_t)e * 5 + 1 + k) * M_ + tid];
                    c = fmaf(f, cc, c);
                }
                float h = o_ * tanhf(c);
                out[(size_t)e * M_ + tid] = c;
                out[(size_t)NCTX * M_ + (size_t)e * M_ + tid] = h;
            }
        }
    }
}

// ---------------------------------------------------------------------------
// Kernel D: leaf-type and zero-type ctx elements
// ---------------------------------------------------------------------------
__global__ void finish_kernel(float* __restrict__ out) {
    int idx = blockIdx.x * blockDim.x + threadIdx.x;
    if (idx >= NCTX * M_) return;
    int e = idx / M_;
    int m = idx - e * M_;
    int t = g_type[e];
    if (t == 2) return;
    float c = 0.f, h = 0.f;
    if (t == 1) {
        c = g_c[(size_t)e * 5 * M_ + m];
        h = g_h[(size_t)e * 5 * M_ + m];
    }
    out[idx] = c;
    out[(size_t)NCTX * M_ + idx] = h;
}

// ---------------------------------------------------------------------------
extern "C" void kernel_launch(void* const* d_in, const int* in_sizes, int n_in,
                              void* d_out, int out_size) {
    const float* embed     = (const float*)d_in[0];
    const float* W_leaf    = (const float*)d_in[1];
    const float* b_leaf    = (const float*)d_in[2];
    const float* W_iou     = (const float*)d_in[3];
    const float* U_iou     = (const float*)d_in[4];
    const float* b_iou     = (const float*)d_in[5];
    const float* W_f       = (const float*)d_in[6];
    const float* U_f       = (const float*)d_in[7];
    const float* b_f       = (const float*)d_in[8];
    const int*   leaf_idx  = (const int*)d_in[9];
    const int*   dep_word  = (const int*)d_in[10];
    const int*   dep_child = (const int*)d_in[11];
    const int*   ctx_idx   = (const int*)d_in[12];
    float* out = (float*)d_out;

    cudaFuncSetAttribute(leaf_gemm_kernel,
                         cudaFuncAttributeMaxDynamicSharedMemorySize, SMEM_GEMM);

    build_jobs_kernel<<<(NCTX + 255) / 256, 256>>>(ctx_idx, dep_word, dep_child);
    prep_w_frag_kernel<<<(KCH * NT * 32 + 255) / 256, 256>>>(W_leaf);
    prep_x_frag_kernel<<<(NMT * KCH * 32 + 255) / 256, 256>>>(embed, leaf_idx);
    leaf_gemm_kernel<<<NJOB / 32, 128, SMEM_GEMM>>>(b_leaf);
    dep_kernel<<<NCTX / TC, 160>>>(embed, W_iou, U_iou, b_iou, W_f, U_f, b_f, out);
    finish_kernel<<<(NCTX * M_ + 255) / 256, 256>>>(out);
}

// round 14
// speedup vs baseline: 1.6092x; 1.6092x over previous
#include <cuda_runtime.h>
#include <cuda_bf16.h>
#include <math.h>
#include <stdint.h>

// Problem constants
#define V_    50000
#define IN_   300
#define M_    150
#define G3_   450      // 3*M
#define NL_   200000
#define D_    6
#define N_    40000
#define K_    4
#define B_    64
#define S_    64
#define NCTX  (B_*S_)          // 4096
#define NJOB  (NCTX*5)         // 20480

// GEMM tiling (fragment-order operands)
#define NP    480              // n padded to 60*8
#define NT    60               // n8 tiles
#define NTG   15               // n8 tiles per warp (4 n-groups)
#define KCH   19               // k16 chunks; k up to 303 zero-guarded vs IN_=300
#define NMT   (NJOB/16)        // 1280 m16 tiles
#define NSTG  (2*KCH)          // 38 staged B chunks: 0..18 = Wfh (Ah+Al), 19..37 = Wfl (Ah)
#define BCHUNK4 (NT*32/2)      // 960 uint4 per staged B chunk (15360 B)
#define SAC   488              // smem acc row stride (floats)
#define SMEM_GEMM (32 * SAC * 4)   // 62464 B dynamic smem (covers 2*15360 B staging)

// dep kernel tiling (unchanged from R8)
#define TC 8
#define PC (TC/2)
#define SDP 4
#define SHT 4

// Scratch (device globals — no allocation allowed)
__device__ int   g_job[NJOB];
__device__ int   g_type[NCTX];
__device__ int   g_word[NCTX];
__device__ float g_c[(size_t)NJOB * M_];
__device__ float g_h[(size_t)NJOB * M_];
__device__ uint4 g_Afh[(size_t)NMT * KCH * 32];    // A fragments, hi plane
__device__ uint4 g_Afl[(size_t)NMT * KCH * 32];    // A fragments, lo plane
__device__ uint2 g_Wfh[(size_t)KCH * NT * 32];     // B fragments, hi plane
__device__ uint2 g_Wfl[(size_t)KCH * NT * 32];     // B fragments, lo plane

__device__ __forceinline__ float sigm(float x) { return 1.0f / (1.0f + expf(-x)); }

__device__ __forceinline__ unsigned long long pack2(float lo, float hi) {
    unsigned long long r;
    asm("mov.b64 %0, {%1, %2};" : "=l"(r) : "f"(lo), "f"(hi));
    return r;
}
__device__ __forceinline__ void unpack2(unsigned long long v, float& lo, float& hi) {
    asm("mov.b64 {%0, %1}, %2;" : "=f"(lo), "=f"(hi) : "l"(v));
}
__device__ __forceinline__ unsigned long long fma2(unsigned long long a,
                                                   unsigned long long b,
                                                   unsigned long long c) {
    unsigned long long d;
    asm("fma.rn.f32x2 %0, %1, %2, %3;" : "=l"(d) : "l"(a), "l"(b), "l"(c));
    return d;
}
__device__ __forceinline__ unsigned long long add2(unsigned long long a,
                                                   unsigned long long b) {
    unsigned long long d;
    asm("add.rn.f32x2 %0, %1, %2;" : "=l"(d) : "l"(a), "l"(b));
    return d;
}

__device__ __forceinline__ uint32_t pack_bf2(float x0, float x1) {
    __nv_bfloat162 v = __floats2bfloat162_rn(x0, x1);
    return *reinterpret_cast<uint32_t*>(&v);
}
__device__ __forceinline__ void split2(float x, float& hi, float& lo) {
    __nv_bfloat16 h = __float2bfloat16(x);
    hi = __bfloat162float(h);
    lo = x - hi;
}
__device__ __forceinline__ void cp_async16(void* smem_dst, const void* gsrc) {
    uint32_t s = (uint32_t)__cvta_generic_to_shared(smem_dst);
    asm volatile("cp.async.ca.shared.global [%0], [%1], 16;" :: "r"(s), "l"(gsrc));
}

// ---------------------------------------------------------------------------
// Kernel A: classify each ctx element, build the leaf-job list
// ---------------------------------------------------------------------------
__global__ void build_jobs_kernel(const int* __restrict__ ctx,
                                  const int* __restrict__ dep_word,
                                  const int* __restrict__ dep_child) {
    int e = blockIdx.x * blockDim.x + threadIdx.x;
    if (e >= NCTX) return;
    int s = ctx[e];
    int base = e * 5;
    int j[5] = {-1, -1, -1, -1, -1};
    int type = 0, word = 0;
    if (s == 0) {
        type = 0;
    } else if (s <= NL_) {
        type = 1;
        j[0] = s - 1;
    } else {
        type = 2;
        int node = s - 1 - NL_;
        word = dep_word[node];
        #pragma unroll
        for (int k = 0; k < K_; k++) {
            int cs = dep_child[node * K_ + k];
            j[1 + k] = (cs >= 1 && cs <= NL_) ? (cs - 1) : -1;
        }
    }
    #pragma unroll
    for (int q = 0; q < 5; q++) g_job[base + q] = j[q];
    g_type[e] = type;
    g_word[e] = word;
}

// ---------------------------------------------------------------------------
// prep_w_frag: W_leaf -> mma B fragments (hi/lo), fragment-order layout.
// ---------------------------------------------------------------------------
__global__ void prep_w_frag_kernel(const float* __restrict__ Wl) {
    int idx = blockIdx.x * blockDim.x + threadIdx.x;   // over KCH*NT*32
    if (idx >= KCH * NT * 32) return;
    int kc   = idx / (NT * 32);
    int r    = idx - kc * (NT * 32);
    int nt   = r >> 5;
    int lane = r & 31;
    int gid  = lane >> 2;
    int tig  = lane & 3;
    int n  = nt * 8 + gid;
    int k0 = kc * 16 + 2 * tig;
    float w00 = 0.f, w01 = 0.f, w10 = 0.f, w11 = 0.f;
    if (n < G3_) {
        if (k0     < IN_) w00 = Wl[(size_t)k0 * G3_ + n];
        if (k0 + 1 < IN_) w01 = Wl[(size_t)(k0 + 1) * G3_ + n];
        if (k0 + 8 < IN_) w10 = Wl[(size_t)(k0 + 8) * G3_ + n];
        if (k0 + 9 < IN_) w11 = Wl[(size_t)(k0 + 9) * G3_ + n];
    }
    float h00, l00, h01, l01, h10, l10, h11, l11;
    split2(w00, h00, l00); split2(w01, h01, l01);
    split2(w10, h10, l10); split2(w11, h11, l11);
    g_Wfh[idx] = make_uint2(pack_bf2(h00, h01), pack_bf2(h10, h11));
    g_Wfl[idx] = make_uint2(pack_bf2(l00, l01), pack_bf2(l10, l11));
}

// ---------------------------------------------------------------------------
// prep_x_frag: gathered embeddings -> mma A fragments (hi/lo).
// ---------------------------------------------------------------------------
__global__ void prep_x_frag_kernel(const float* __restrict__ embed,
                                   const int*   __restrict__ leaf_idx) {
    int idx = blockIdx.x * blockDim.x + threadIdx.x;   // over NMT*KCH*32
    if (idx >= NMT * KCH * 32) return;
    int mt   = idx / (KCH * 32);
    int r    = idx - mt * (KCH * 32);
    int kc   = r >> 5;
    int lane = r & 31;
    int gid  = lane >> 2;
    int tig  = lane & 3;
    int j0 = mt * 16 + gid;
    int j1 = j0 + 8;
    int k  = kc * 16 + 2 * tig;

    int jb0 = g_job[j0], jb1 = g_job[j1];
    float x00 = 0.f, x01 = 0.f, x08 = 0.f, x09 = 0.f;
    float y00 = 0.f, y01 = 0.f, y08 = 0.f, y09 = 0.f;
    if (jb0 >= 0) {
        const float* row = embed + (size_t)leaf_idx[jb0] * IN_;
        if (k     < IN_) x00 = row[k];
        if (k + 1 < IN_) x01 = row[k + 1];
        if (k + 8 < IN_) x08 = row[k + 8];
        if (k + 9 < IN_) x09 = row[k + 9];
    }
    if (jb1 >= 0) {
        const float* row = embed + (size_t)leaf_idx[jb1] * IN_;
        if (k     < IN_) y00 = row[k];
        if (k + 1 < IN_) y01 = row[k + 1];
        if (k + 8 < IN_) y08 = row[k + 8];
        if (k + 9 < IN_) y09 = row[k + 9];
    }
    float hx00,lx00,hx01,lx01,hx08,lx08,hx09,lx09;
    float hy00,ly00,hy01,ly01,hy08,ly08,hy09,ly09;
    split2(x00,hx00,lx00); split2(x01,hx01,lx01);
    split2(x08,hx08,lx08); split2(x09,hx09,lx09);
    split2(y00,hy00,ly00); split2(y01,hy01,ly01);
    split2(y08,hy08,ly08); split2(y09,hy09,ly09);
    g_Afh[idx] = make_uint4(pack_bf2(hx00,hx01), pack_bf2(hy00,hy01),
                            pack_bf2(hx08,hx09), pack_bf2(hy08,hy09));
    g_Afl[idx] = make_uint4(pack_bf2(lx00,lx01), pack_bf2(ly00,ly01),
                            pack_bf2(lx08,lx09), pack_bf2(ly08,ly09));
}

// ---------------------------------------------------------------------------
// leaf_gemm: 3-plane bf16 split GEMM; B chunks staged block-wide in smem via
// cp.async double buffering; planes hi*hi and lo*hi share each staged Wfh
// chunk. Block = 256 thr (8 warps) = 2 m-tiles x 60 n-tiles; warp = 1 m-tile
// x 15 n-tiles (60 acc regs). Fused epilogue. Grid = NJOB/32 = 640.
// ---------------------------------------------------------------------------
#define MMA_ACC(C, A, Bv)                                                      \
    asm volatile(                                                              \
        "mma.sync.aligned.m16n8k16.row.col.f32.bf16.bf16.f32 "                 \
        "{%0,%1,%2,%3}, {%4,%5,%6,%7}, {%8,%9}, {%0,%1,%2,%3};"                \
        : "+f"((C)[0]), "+f"((C)[1]), "+f"((C)[2]), "+f"((C)[3])               \
        : "r"((A).x), "r"((A).y), "r"((A).z), "r"((A).w),                      \
          "r"((Bv).x), "r"((Bv).y))

__global__ void __launch_bounds__(256, 2)
leaf_gemm_kernel(const float* __restrict__ bl) {
    extern __shared__ __align__(16) float s_mem[];
    uint4* sB = reinterpret_cast<uint4*>(s_mem);   // [2][BCHUNK4]

    const int tid  = threadIdx.x;
    const int lane = tid & 31;
    const int warp = tid >> 5;
    const int ng   = warp & 3;        // n-group 0..3
    const int mt_l = warp >> 2;       // m-tile within block 0..1
    const int mtile = blockIdx.x * 2 + mt_l;
    const int nt0   = ng * NTG;
    const int gid   = lane >> 2;
    const int tig   = lane & 3;

    float c[NTG][4];
    #pragma unroll
    for (int t = 0; t < NTG; t++) {
        c[t][0]=0.f; c[t][1]=0.f; c[t][2]=0.f; c[t][3]=0.f;
    }

    const uint4* Ah = g_Afh + (size_t)mtile * KCH * 32 + lane;
    const uint4* Al = g_Afl + (size_t)mtile * KCH * 32 + lane;

    // stage s: s<KCH -> Wfh chunk s (mma Ah then Al); s>=KCH -> Wfl chunk s-KCH (mma Ah)
    auto issue_stage = [&](int s) {
        const uint4* src = (s < KCH)
            ? reinterpret_cast<const uint4*>(g_Wfh) + (size_t)s * BCHUNK4
            : reinterpret_cast<const uint4*>(g_Wfl) + (size_t)(s - KCH) * BCHUNK4;
        uint4* dst = sB + (size_t)(s & 1) * BCHUNK4;
        #pragma unroll
        for (int i = 0; i < 4; i++) {
            int o = tid + i * 256;
            if (o < BCHUNK4) cp_async16(dst + o, src + o);
        }
        asm volatile("cp.async.commit_group;" ::: "memory");
    };

    issue_stage(0);
    uint4 ah = Ah[0];
    uint4 al = Al[0];

    for (int s = 0; s < NSTG; s++) {
        if (s + 1 < NSTG) issue_stage(s + 1);
        // prefetch next stage's A fragments
        uint4 ah_n, al_n;
        if (s + 1 < NSTG) {
            int kcn = (s + 1 < KCH) ? (s + 1) : (s + 1 - KCH);
            ah_n = Ah[kcn * 32];
            if (s + 1 < KCH) al_n = Al[kcn * 32];
        }
        if (s + 1 < NSTG) asm volatile("cp.async.wait_group 1;" ::: "memory");
        else              asm volatile("cp.async.wait_group 0;" ::: "memory");
        __syncthreads();

        const uint2* Bs = reinterpret_cast<const uint2*>(sB + (size_t)(s & 1) * BCHUNK4);
        #pragma unroll
        for (int t = 0; t < NTG; t++) {
            uint2 b = Bs[(nt0 + t) * 32 + lane];
            MMA_ACC(c[t], ah, b);
        }
        if (s < KCH) {                       // Wfh chunk: also lo*hi plane
            #pragma unroll
            for (int t = 0; t < NTG; t++) {
                uint2 b = Bs[(nt0 + t) * 32 + lane];   // cheap LDS re-read
                MMA_ACC(c[t], al, b);
            }
        }
        __syncthreads();                     // protect buffer (s&1) before reuse at s+2
        ah = ah_n;
        al = al_n;
    }

    // stage accumulators to smem (reuses staging region; all mma done)
    #pragma unroll
    for (int t = 0; t < NTG; t++) {
        int n0 = (nt0 + t) * 8 + 2 * tig;
        int r0 = mt_l * 16 + gid;
        *reinterpret_cast<float2*>(&s_mem[(r0    ) * SAC + n0]) = make_float2(c[t][0], c[t][1]);
        *reinterpret_cast<float2*>(&s_mem[(r0 + 8) * SAC + n0]) = make_float2(c[t][2], c[t][3]);
    }
    __syncthreads();

    // fused epilogue: gates for 32 jobs x 150 lanes
    const int jb32 = blockIdx.x * 32;
    for (int idx = tid; idx < 32 * M_; idx += 256) {
        int lj = idx / M_;
        int m  = idx - lj * M_;
        int j  = jb32 + lj;
        float cc = 0.f, hh = 0.f;
        if (g_job[j] >= 0) {
            float i_ = sigm(s_mem[lj * SAC + m]           + bl[m]);
            float o_ = sigm(s_mem[lj * SAC + M_ + m]      + bl[M_ + m]);
            float u_ = tanhf(s_mem[lj * SAC + 2 * M_ + m] + bl[2 * M_ + m]);
            cc = i_ * u_;
            hh = o_ * tanhf(cc);
        }
        g_c[(size_t)j * M_ + m] = cc;
        g_h[(size_t)j * M_ + m] = hh;
    }
}

// ---------------------------------------------------------------------------
// Kernel C: dep-node cell (unchanged from R8: pair-packed f32x2, occ 3)
// ---------------------------------------------------------------------------
__global__ void __launch_bounds__(160, 3)
dep_kernel(const float* __restrict__ embed,
           const float* __restrict__ Wiou,
           const float* __restrict__ Uiou,
           const float* __restrict__ biou,
           const float* __restrict__ Wf,
           const float* __restrict__ Uf,
           const float* __restrict__ bf,
           float* __restrict__ out) {
    __shared__ __align__(16) float2 sxd2[IN_ * SDP];
    __shared__ __align__(16) float2 sh2 [K_ * M_ * SHT];
    __shared__ __align__(16) float2 shs2[M_ * SDP];
    __shared__ int styp[TC];
    __shared__ int sword[TC];

    const int eb  = blockIdx.x * TC;
    const int tid = threadIdx.x;

    if (tid < TC) {
        styp[tid]  = g_type[eb + tid];
        sword[tid] = g_word[eb + tid];
    }
    __syncthreads();

    for (int idx = tid; idx < PC * IN_; idx += blockDim.x) {
        int p = idx / IN_;
        int t = idx - p * IN_;
        int l0 = 2 * p, l1 = 2 * p + 1;
        float a = (styp[l0] == 2) ? embed[(size_t)sword[l0] * IN_ + t] : 0.0f;
        float b = (styp[l1] == 2) ? embed[(size_t)sword[l1] * IN_ + t] : 0.0f;
        sxd2[t * SDP + p] = make_float2(a, b);
    }
    for (int idx = tid; idx < PC * K_ * M_; idx += blockDim.x) {
        int pk = idx / M_;
        int t  = idx - pk * M_;
        int p  = pk / K_;
        int k  = pk - p * K_;
        int l0 = 2 * p, l1 = 2 * p + 1;
        float a = (styp[l0] == 2) ? g_h[((size_t)(eb + l0) * 5 + 1 + k) * M_ + t] : 0.0f;
        float b = (styp[l1] == 2) ? g_h[((size_t)(eb + l1) * 5 + 1 + k) * M_ + t] : 0.0f;
        sh2[(k * M_ + t) * SHT + p] = make_float2(a, b);
    }
    __syncthreads();
    for (int idx = tid; idx < PC * M_; idx += blockDim.x) {
        int p = idx / M_;
        int t = idx - p * M_;
        const unsigned long long* s64 =
            reinterpret_cast<const unsigned long long*>(sh2);
        unsigned long long s = add2(add2(s64[(0 * M_ + t) * SHT + p],
                                         s64[(1 * M_ + t) * SHT + p]),
                                    add2(s64[(2 * M_ + t) * SHT + p],
                                         s64[(3 * M_ + t) * SHT + p]));
        reinterpret_cast<unsigned long long*>(shs2)[t * SDP + p] = s;
    }
    __syncthreads();

    if (tid < M_) {
        unsigned long long ai[PC], ao[PC], au[PC], axf[PC], af[PC][K_];
        #pragma unroll
        for (int p = 0; p < PC; p++) {
            ai[p] = 0ull; ao[p] = 0ull; au[p] = 0ull; axf[p] = 0ull;
            #pragma unroll
            for (int k = 0; k < K_; k++) af[p][k] = 0ull;
        }

        #pragma unroll 2
        for (int t = 0; t < IN_; t++) {
            float wi = __ldg(Wiou + (size_t)t * G3_ + tid);
            float wo = __ldg(Wiou + (size_t)t * G3_ + M_ + tid);
            float wu = __ldg(Wiou + (size_t)t * G3_ + 2 * M_ + tid);
            float wf = __ldg(Wf   + (size_t)t * M_ + tid);
            unsigned long long wip = pack2(wi, wi);
            unsigned long long wop = pack2(wo, wo);
            unsigned long long wup = pack2(wu, wu);
            unsigned long long wfp = pack2(wf, wf);
            const ulonglong2* row =
                reinterpret_cast<const ulonglong2*>(sxd2 + t * SDP);
            ulonglong2 x01 = row[0];
            ulonglong2 x23 = row[1];
            unsigned long long xv[PC] = {x01.x, x01.y, x23.x, x23.y};
            #pragma unroll
            for (int p = 0; p < PC; p++) {
                ai[p]  = fma2(xv[p], wip, ai[p]);
                ao[p]  = fma2(xv[p], wop, ao[p]);
                au[p]  = fma2(xv[p], wup, au[p]);
                axf[p] = fma2(xv[p], wfp, axf[p]);
            }
        }
        #pragma unroll 2
        for (int t = 0; t < M_; t++) {
            float ui = __ldg(Uiou + (size_t)t * G3_ + tid);
            float uo = __ldg(Uiou + (size_t)t * G3_ + M_ + tid);
            float uu = __ldg(Uiou + (size_t)t * G3_ + 2 * M_ + tid);
            float uf = __ldg(Uf   + (size_t)t * M_ + tid);
            unsigned long long uip = pack2(ui, ui);
            unsigned long long uop = pack2(uo, uo);
            unsigned long long uup = pack2(uu, uu);
            unsigned long long ufp = pack2(uf, uf);
            const ulonglong2* srow =
                reinterpret_cast<const ulonglong2*>(shs2 + t * SDP);
            ulonglong2 h01 = srow[0];
            ulonglong2 h23 = srow[1];
            unsigned long long hv[PC] = {h01.x, h01.y, h23.x, h23.y};
            #pragma unroll
            for (int p = 0; p < PC; p++) {
                ai[p] = fma2(hv[p], uip, ai[p]);
                ao[p] = fma2(hv[p], uop, ao[p]);
                au[p] = fma2(hv[p], uup, au[p]);
            }
            #pragma unroll
            for (int k = 0; k < K_; k++) {
                const ulonglong2* krow =
                    reinterpret_cast<const ulonglong2*>(sh2 + (k * M_ + t) * SHT);
                ulonglong2 k01 = krow[0];
                ulonglong2 k23 = krow[1];
                unsigned long long kv[PC] = {k01.x, k01.y, k23.x, k23.y};
                #pragma unroll
                for (int p = 0; p < PC; p++)
                    af[p][k] = fma2(kv[p], ufp, af[p][k]);
            }
        }

        const float bi = biou[tid], bo = biou[M_ + tid], bu = biou[2 * M_ + tid];
        const float bff = bf[tid];
        #pragma unroll
        for (int p = 0; p < PC; p++) {
            float i0, i1, o0, o1, u0, u1, x0, x1;
            unpack2(ai[p], i0, i1);
            unpack2(ao[p], o0, o1);
            unpack2(au[p], u0, u1);
            unpack2(axf[p], x0, x1);
            float f0[K_], f1[K_];
            #pragma unroll
            for (int k = 0; k < K_; k++) unpack2(af[p][k], f0[k], f1[k]);
            #pragma unroll
            for (int half = 0; half < 2; half++) {
                int l = 2 * p + half;
                if (styp[l] != 2) continue;
                int e = eb + l;
                float i_ = sigm((half ? i1 : i0) + bi);
                float o_ = sigm((half ? o1 : o0) + bo);
                float u_ = tanhf((half ? u1 : u0) + bu);
                float xf = half ? x1 : x0;
                float c  = i_ * u_;
                #pragma unroll
                for (int k = 0; k < K_; k++) {
                    float f  = sigm(xf + (half ? f1[k] : f0[k]) + bff);
                    float cc = g_c[((size_t)e * 5 + 1 + k) * M_ + tid];
                    c = fmaf(f, cc, c);
                }
                float h = o_ * tanhf(c);
                out[(size_t)e * M_ + tid] = c;
                out[(size_t)NCTX * M_ + (size_t)e * M_ + tid] = h;
            }
        }
    }
}

// ---------------------------------------------------------------------------
// Kernel D: leaf-type and zero-type ctx elements
// ---------------------------------------------------------------------------
__global__ void finish_kernel(float* __restrict__ out) {
    int idx = blockIdx.x * blockDim.x + threadIdx.x;
    if (idx >= NCTX * M_) return;
    int e = idx / M_;
    int m = idx - e * M_;
    int t = g_type[e];
    if (t == 2) return;
    float c = 0.f, h = 0.f;
    if (t == 1) {
        c = g_c[(size_t)e * 5 * M_ + m];
        h = g_h[(size_t)e * 5 * M_ + m];
    }
    out[idx] = c;
    out[(size_t)NCTX * M_ + idx] = h;
}

// ---------------------------------------------------------------------------
extern "C" void kernel_launch(void* const* d_in, const int* in_sizes, int n_in,
                              void* d_out, int out_size) {
    const float* embed     = (const float*)d_in[0];
    const float* W_leaf    = (const float*)d_in[1];
    const float* b_leaf    = (const float*)d_in[2];
    const float* W_iou     = (const float*)d_in[3];
    const float* U_iou     = (const float*)d_in[4];
    const float* b_iou     = (const float*)d_in[5];
    const float* W_f       = (const float*)d_in[6];
    const float* U_f       = (const float*)d_in[7];
    const float* b_f       = (const float*)d_in[8];
    const int*   leaf_idx  = (const int*)d_in[9];
    const int*   dep_word  = (const int*)d_in[10];
    const int*   dep_child = (const int*)d_in[11];
    const int*   ctx_idx   = (const int*)d_in[12];
    float* out = (float*)d_out;

    cudaFuncSetAttribute(leaf_gemm_kernel,
                         cudaFuncAttributeMaxDynamicSharedMemorySize, SMEM_GEMM);

    build_jobs_kernel<<<(NCTX + 255) / 256, 256>>>(ctx_idx, dep_word, dep_child);
    prep_w_frag_kernel<<<(KCH * NT * 32 + 255) / 256, 256>>>(W_leaf);
    prep_x_frag_kernel<<<(NMT * KCH * 32 + 255) / 256, 256>>>(embed, leaf_idx);
    leaf_gemm_kernel<<<NJOB / 32, 256, SMEM_GEMM>>>(b_leaf);
    dep_kernel<<<NCTX / TC, 160>>>(embed, W_iou, U_iou, b_iou, W_f, U_f, b_f, out);
    finish_kernel<<<(NCTX * M_ + 255) / 256, 256>>>(out);
}

// round 17
// speedup vs baseline: 1.9997x; 1.2427x over previous
#include <cuda_runtime.h>
#include <cuda_bf16.h>
#include <math.h>
#include <stdint.h>

// Problem constants
#define V_    50000
#define IN_   300
#define M_    150
#define G3_   450      // 3*M
#define NL_   200000
#define D_    6
#define N_    40000
#define K_    4
#define B_    64
#define S_    64
#define NCTX  (B_*S_)          // 4096
#define NJOB  (NCTX*5)         // 20480 worst case

// GEMM tiling (fragment-order operands)
#define NP    480              // n padded to 60*8
#define NT    60               // n8 tiles
#define NTG   15               // n8 tiles per warp (4 n-groups)
#define KCH   19               // k16 chunks; k up to 303 zero-guarded vs IN_=300
#define NMT   (NJOB/16)        // 1280 m16 tiles (worst case)
#define NSTG  (2*KCH)          // 38 staged B chunks: 0..18 = Wfh (Ah+Al), 19..37 = Wfl (Ah)
#define BCHUNK4 (NT*32/2)      // 960 uint4 per staged B chunk (15360 B)
#define SAC   488              // smem acc row stride (floats)
#define SMEM_GEMM (32 * SAC * 4)   // 62464 B dynamic smem

// dep kernel tiling
#define TC 8
#define PC (TC/2)
#define SDP 4
#define SHT 4

// Scratch (device globals — no allocation allowed)
__device__ int   g_nact;               // number of compacted active jobs
__device__ int   g_slot[NJOB];         // ctx-element job -> compact slot (-1 none)
__device__ int   g_jobword[NJOB];      // compact slot -> WORD index (embed row)
__device__ int   g_type[NCTX];         // 0=zero slot, 1=leaf, 2=dep
__device__ int   g_word[NCTX];         // word idx for dep elements
__device__ float g_c[(size_t)NJOB * M_];
__device__ float g_h[(size_t)NJOB * M_];
__device__ uint4 g_Afh[(size_t)NMT * KCH * 32];    // A fragments, hi plane
__device__ uint4 g_Afl[(size_t)NMT * KCH * 32];    // A fragments, lo plane
__device__ uint2 g_Wfh[(size_t)KCH * NT * 32];     // B fragments, hi plane
__device__ uint2 g_Wfl[(size_t)KCH * NT * 32];     // B fragments, lo plane

__device__ __forceinline__ float sigm(float x) { return 1.0f / (1.0f + expf(-x)); }

__device__ __forceinline__ unsigned long long pack2(float lo, float hi) {
    unsigned long long r;
    asm("mov.b64 %0, {%1, %2};" : "=l"(r) : "f"(lo), "f"(hi));
    return r;
}
__device__ __forceinline__ void unpack2(unsigned long long v, float& lo, float& hi) {
    asm("mov.b64 {%0, %1}, %2;" : "=f"(lo), "=f"(hi) : "l"(v));
}
__device__ __forceinline__ unsigned long long fma2(unsigned long long a,
                                                   unsigned long long b,
                                                   unsigned long long c) {
    unsigned long long d;
    asm("fma.rn.f32x2 %0, %1, %2, %3;" : "=l"(d) : "l"(a), "l"(b), "l"(c));
    return d;
}
__device__ __forceinline__ unsigned long long add2(unsigned long long a,
                                                   unsigned long long b) {
    unsigned long long d;
    asm("add.rn.f32x2 %0, %1, %2;" : "=l"(d) : "l"(a), "l"(b));
    return d;
}

__device__ __forceinline__ uint32_t pack_bf2(float x0, float x1) {
    __nv_bfloat162 v = __floats2bfloat162_rn(x0, x1);
    return *reinterpret_cast<uint32_t*>(&v);
}
__device__ __forceinline__ void split2(float x, float& hi, float& lo) {
    __nv_bfloat16 h = __float2bfloat16(x);
    hi = __bfloat162float(h);
    lo = x - hi;
}
__device__ __forceinline__ void cp_async16(void* smem_dst, const void* gsrc) {
    uint32_t s = (uint32_t)__cvta_generic_to_shared(smem_dst);
    asm volatile("cp.async.ca.shared.global [%0], [%1], 16;" :: "r"(s), "l"(gsrc));
}

// ---------------------------------------------------------------------------
// init: zero the compaction counter
// ---------------------------------------------------------------------------
__global__ void init_kernel() {
    if (threadIdx.x == 0 && blockIdx.x == 0) g_nact = 0;
}

// ---------------------------------------------------------------------------
// Kernel A: classify ctx elements, build COMPACTED job list via atomicAdd.
// g_jobword stores the WORD index (leaf_idx[leaf]) — the embed row to gather.
// ---------------------------------------------------------------------------
__global__ void build_jobs_kernel(const int* __restrict__ ctx,
                                  const int* __restrict__ dep_word,
                                  const int* __restrict__ dep_child,
                                  const int* __restrict__ leaf_idx) {
    int e = blockIdx.x * blockDim.x + threadIdx.x;
    if (e >= NCTX) return;
    int s = ctx[e];
    int base = e * 5;
    int j[5] = {-1, -1, -1, -1, -1};
    int type = 0, word = 0;
    if (s == 0) {
        type = 0;
    } else if (s <= NL_) {
        type = 1;
        j[0] = s - 1;
    } else {
        type = 2;
        int node = s - 1 - NL_;
        word = dep_word[node];
        #pragma unroll
        for (int k = 0; k < K_; k++) {
            int cs = dep_child[node * K_ + k];
            j[1 + k] = (cs >= 1 && cs <= NL_) ? (cs - 1) : -1;
        }
    }
    int cnt = 0;
    #pragma unroll
    for (int q = 0; q < 5; q++) cnt += (j[q] >= 0);
    int slot = (cnt > 0) ? atomicAdd(&g_nact, cnt) : 0;
    #pragma unroll
    for (int q = 0; q < 5; q++) {
        if (j[q] >= 0) {
            g_slot[base + q] = slot;
            g_jobword[slot]  = leaf_idx[j[q]];    // word index for embed gather
            slot++;
        } else {
            g_slot[base + q] = -1;
        }
    }
    g_type[e] = type;
    g_word[e] = word;
}

// ---------------------------------------------------------------------------
// prep_w_frag: W_leaf -> mma B fragments (hi/lo), fragment-order layout.
// ---------------------------------------------------------------------------
__global__ void prep_w_frag_kernel(const float* __restrict__ Wl) {
    int idx = blockIdx.x * blockDim.x + threadIdx.x;   // over KCH*NT*32
    if (idx >= KCH * NT * 32) return;
    int kc   = idx / (NT * 32);
    int r    = idx - kc * (NT * 32);
    int nt   = r >> 5;
    int lane = r & 31;
    int gid  = lane >> 2;
    int tig  = lane & 3;
    int n  = nt * 8 + gid;
    int k0 = kc * 16 + 2 * tig;
    float w00 = 0.f, w01 = 0.f, w10 = 0.f, w11 = 0.f;
    if (n < G3_) {
        if (k0     < IN_) w00 = Wl[(size_t)k0 * G3_ + n];
        if (k0 + 1 < IN_) w01 = Wl[(size_t)(k0 + 1) * G3_ + n];
        if (k0 + 8 < IN_) w10 = Wl[(size_t)(k0 + 8) * G3_ + n];
        if (k0 + 9 < IN_) w11 = Wl[(size_t)(k0 + 9) * G3_ + n];
    }
    float h00, l00, h01, l01, h10, l10, h11, l11;
    split2(w00, h00, l00); split2(w01, h01, l01);
    split2(w10, h10, l10); split2(w11, h11, l11);
    g_Wfh[idx] = make_uint2(pack_bf2(h00, h01), pack_bf2(h10, h11));
    g_Wfl[idx] = make_uint2(pack_bf2(l00, l01), pack_bf2(l10, l11));
}

// ---------------------------------------------------------------------------
// prep_x_frag: compacted gathered embeddings -> mma A fragments (hi/lo).
// Slots >= nact (up to pad32) are zero-filled; beyond pad32 skipped entirely.
// ---------------------------------------------------------------------------
__global__ void prep_x_frag_kernel(const float* __restrict__ embed) {
    int nact = g_nact;
    int pad32 = (nact + 31) & ~31;
    int idx = blockIdx.x * blockDim.x + threadIdx.x;   // over NMT*KCH*32
    if (idx >= NMT * KCH * 32) return;
    int mt   = idx / (KCH * 32);
    if (mt * 16 >= pad32) return;                      // never read by gemm
    int r    = idx - mt * (KCH * 32);
    int kc   = r >> 5;
    int lane = r & 31;
    int gid  = lane >> 2;
    int tig  = lane & 3;
    int j0 = mt * 16 + gid;
    int j1 = j0 + 8;
    int k  = kc * 16 + 2 * tig;

    float x00 = 0.f, x01 = 0.f, x08 = 0.f, x09 = 0.f;
    float y00 = 0.f, y01 = 0.f, y08 = 0.f, y09 = 0.f;
    if (j0 < nact) {
        const float* row = embed + (size_t)g_jobword[j0] * IN_;
        if (k     < IN_) x00 = row[k];
        if (k + 1 < IN_) x01 = row[k + 1];
        if (k + 8 < IN_) x08 = row[k + 8];
        if (k + 9 < IN_) x09 = row[k + 9];
    }
    if (j1 < nact) {
        const float* row = embed + (size_t)g_jobword[j1] * IN_;
        if (k     < IN_) y00 = row[k];
        if (k + 1 < IN_) y01 = row[k + 1];
        if (k + 8 < IN_) y08 = row[k + 8];
        if (k + 9 < IN_) y09 = row[k + 9];
    }
    float hx00,lx00,hx01,lx01,hx08,lx08,hx09,lx09;
    float hy00,ly00,hy01,ly01,hy08,ly08,hy09,ly09;
    split2(x00,hx00,lx00); split2(x01,hx01,lx01);
    split2(x08,hx08,lx08); split2(x09,hx09,lx09);
    split2(y00,hy00,ly00); split2(y01,hy01,ly01);
    split2(y08,hy08,ly08); split2(y09,hy09,ly09);
    g_Afh[idx] = make_uint4(pack_bf2(hx00,hx01), pack_bf2(hy00,hy01),
                            pack_bf2(hx08,hx09), pack_bf2(hy08,hy09));
    g_Afl[idx] = make_uint4(pack_bf2(lx00,lx01), pack_bf2(ly00,ly01),
                            pack_bf2(lx08,lx09), pack_bf2(ly08,ly09));
}

// ---------------------------------------------------------------------------
// leaf_gemm: 3-plane bf16 split GEMM; B staged block-wide in smem (cp.async
// double buffer); Wfh chunks serve hi*hi AND lo*hi planes. Early-exit for
// blocks beyond the compacted job count. Fused epilogue.
// Block = 256 thr (8 warps) = 2 m-tiles x 60 n-tiles. Grid = 640 (static).
// ---------------------------------------------------------------------------
#define MMA_ACC(C, A, Bv)                                                      \
    asm volatile(                                                              \
        "mma.sync.aligned.m16n8k16.row.col.f32.bf16.bf16.f32 "                 \
        "{%0,%1,%2,%3}, {%4,%5,%6,%7}, {%8,%9}, {%0,%1,%2,%3};"                \
        : "+f"((C)[0]), "+f"((C)[1]), "+f"((C)[2]), "+f"((C)[3])               \
        : "r"((A).x), "r"((A).y), "r"((A).z), "r"((A).w),                      \
          "r"((Bv).x), "r"((Bv).y))

__global__ void __launch_bounds__(256, 2)
leaf_gemm_kernel(const float* __restrict__ bl) {
    const int nact = g_nact;
    if (blockIdx.x * 32 >= nact) return;               // uniform early exit

    extern __shared__ __align__(16) float s_mem[];
    uint4* sB = reinterpret_cast<uint4*>(s_mem);   // [2][BCHUNK4]

    const int tid  = threadIdx.x;
    const int lane = tid & 31;
    const int warp = tid >> 5;
    const int ng   = warp & 3;        // n-group 0..3
    const int mt_l = warp >> 2;       // m-tile within block 0..1
    const int mtile = blockIdx.x * 2 + mt_l;
    const int nt0   = ng * NTG;
    const int gid   = lane >> 2;
    const int tig   = lane & 3;

    float c[NTG][4];
    #pragma unroll
    for (int t = 0; t < NTG; t++) {
        c[t][0]=0.f; c[t][1]=0.f; c[t][2]=0.f; c[t][3]=0.f;
    }

    const uint4* Ah = g_Afh + (size_t)mtile * KCH * 32 + lane;
    const uint4* Al = g_Afl + (size_t)mtile * KCH * 32 + lane;

    auto issue_stage = [&](int s) {
        const uint4* src = (s < KCH)
            ? reinterpret_cast<const uint4*>(g_Wfh) + (size_t)s * BCHUNK4
            : reinterpret_cast<const uint4*>(g_Wfl) + (size_t)(s - KCH) * BCHUNK4;
        uint4* dst = sB + (size_t)(s & 1) * BCHUNK4;
        #pragma unroll
        for (int i = 0; i < 4; i++) {
            int o = tid + i * 256;
            if (o < BCHUNK4) cp_async16(dst + o, src + o);
        }
        asm volatile("cp.async.commit_group;" ::: "memory");
    };

    issue_stage(0);
    uint4 ah = Ah[0];
    uint4 al = Al[0];

    for (int s = 0; s < NSTG; s++) {
        if (s + 1 < NSTG) issue_stage(s + 1);
        uint4 ah_n, al_n;
        if (s + 1 < NSTG) {
            int kcn = (s + 1 < KCH) ? (s + 1) : (s + 1 - KCH);
            ah_n = Ah[kcn * 32];
            if (s + 1 < KCH) al_n = Al[kcn * 32];
        }
        if (s + 1 < NSTG) asm volatile("cp.async.wait_group 1;" ::: "memory");
        else              asm volatile("cp.async.wait_group 0;" ::: "memory");
        __syncthreads();

        const uint2* Bs = reinterpret_cast<const uint2*>(sB + (size_t)(s & 1) * BCHUNK4);
        #pragma unroll
        for (int t = 0; t < NTG; t++) {
            uint2 b = Bs[(nt0 + t) * 32 + lane];
            MMA_ACC(c[t], ah, b);
        }
        if (s < KCH) {
            #pragma unroll
            for (int t = 0; t < NTG; t++) {
                uint2 b = Bs[(nt0 + t) * 32 + lane];
                MMA_ACC(c[t], al, b);
            }
        }
        __syncthreads();
        ah = ah_n;
        al = al_n;
    }

    // stage accumulators to smem (reuses staging region; all mma done)
    #pragma unroll
    for (int t = 0; t < NTG; t++) {
        int n0 = (nt0 + t) * 8 + 2 * tig;
        int r0 = mt_l * 16 + gid;
        *reinterpret_cast<float2*>(&s_mem[(r0    ) * SAC + n0]) = make_float2(c[t][0], c[t][1]);
        *reinterpret_cast<float2*>(&s_mem[(r0 + 8) * SAC + n0]) = make_float2(c[t][2], c[t][3]);
    }
    __syncthreads();

    // fused epilogue: gates for 32 compacted jobs x 150 lanes
    const int jb32 = blockIdx.x * 32;
    for (int idx = tid; idx < 32 * M_; idx += 256) {
        int lj = idx / M_;
        int m  = idx - lj * M_;
        int j  = jb32 + lj;
        float i_ = sigm(s_mem[lj * SAC + m]           + bl[m]);
        float o_ = sigm(s_mem[lj * SAC + M_ + m]      + bl[M_ + m]);
        float u_ = tanhf(s_mem[lj * SAC + 2 * M_ + m] + bl[2 * M_ + m]);
        float cc = i_ * u_;
        float hh = o_ * tanhf(cc);
        g_c[(size_t)j * M_ + m] = cc;
        g_h[(size_t)j * M_ + m] = hh;
    }
}

// ---------------------------------------------------------------------------
// Kernel C: dep-node cell (pair-packed f32x2, occ 3); children via g_slot
// ---------------------------------------------------------------------------
__global__ void __launch_bounds__(160, 3)
dep_kernel(const float* __restrict__ embed,
           const float* __restrict__ Wiou,
           const float* __restrict__ Uiou,
           const float* __restrict__ biou,
           const float* __restrict__ Wf,
           const float* __restrict__ Uf,
           const float* __restrict__ bf,
           float* __restrict__ out) {
    __shared__ __align__(16) float2 sxd2[IN_ * SDP];
    __shared__ __align__(16) float2 sh2 [K_ * M_ * SHT];
    __shared__ __align__(16) float2 shs2[M_ * SDP];
    __shared__ int styp[TC];
    __shared__ int sword[TC];
    __shared__ int sslot[TC][K_];

    const int eb  = blockIdx.x * TC;
    const int tid = threadIdx.x;

    if (tid < TC) {
        styp[tid]  = g_type[eb + tid];
        sword[tid] = g_word[eb + tid];
    }
    if (tid < TC * K_) {
        int l = tid / K_;
        int k = tid - l * K_;
        sslot[l][k] = g_slot[(eb + l) * 5 + 1 + k];
    }
    __syncthreads();

    for (int idx = tid; idx < PC * IN_; idx += blockDim.x) {
        int p = idx / IN_;
        int t = idx - p * IN_;
        int l0 = 2 * p, l1 = 2 * p + 1;
        float a = (styp[l0] == 2) ? embed[(size_t)sword[l0] * IN_ + t] : 0.0f;
        float b = (styp[l1] == 2) ? embed[(size_t)sword[l1] * IN_ + t] : 0.0f;
        sxd2[t * SDP + p] = make_float2(a, b);
    }
    for (int idx = tid; idx < PC * K_ * M_; idx += blockDim.x) {
        int pk = idx / M_;
        int t  = idx - pk * M_;
        int p  = pk / K_;
        int k  = pk - p * K_;
        int l0 = 2 * p, l1 = 2 * p + 1;
        int s0 = sslot[l0][k], s1 = sslot[l1][k];
        float a = (styp[l0] == 2 && s0 >= 0) ? g_h[(size_t)s0 * M_ + t] : 0.0f;
        float b = (styp[l1] == 2 && s1 >= 0) ? g_h[(size_t)s1 * M_ + t] : 0.0f;
        sh2[(k * M_ + t) * SHT + p] = make_float2(a, b);
    }
    __syncthreads();
    for (int idx = tid; idx < PC * M_; idx += blockDim.x) {
        int p = idx / M_;
        int t = idx - p * M_;
        const unsigned long long* s64 =
            reinterpret_cast<const unsigned long long*>(sh2);
        unsigned long long s = add2(add2(s64[(0 * M_ + t) * SHT + p],
                                         s64[(1 * M_ + t) * SHT + p]),
                                    add2(s64[(2 * M_ + t) * SHT + p],
                                         s64[(3 * M_ + t) * SHT + p]));
        reinterpret_cast<unsigned long long*>(shs2)[t * SDP + p] = s;
    }
    __syncthreads();

    if (tid < M_) {
        unsigned long long ai[PC], ao[PC], au[PC], axf[PC], af[PC][K_];
        #pragma unroll
        for (int p = 0; p < PC; p++) {
            ai[p] = 0ull; ao[p] = 0ull; au[p] = 0ull; axf[p] = 0ull;
            #pragma unroll
            for (int k = 0; k < K_; k++) af[p][k] = 0ull;
        }

        #pragma unroll 2
        for (int t = 0; t < IN_; t++) {
            float wi = __ldg(Wiou + (size_t)t * G3_ + tid);
            float wo = __ldg(Wiou + (size_t)t * G3_ + M_ + tid);
            float wu = __ldg(Wiou + (size_t)t * G3_ + 2 * M_ + tid);
            float wf = __ldg(Wf   + (size_t)t * M_ + tid);
            unsigned long long wip = pack2(wi, wi);
            unsigned long long wop = pack2(wo, wo);
            unsigned long long wup = pack2(wu, wu);
            unsigned long long wfp = pack2(wf, wf);
            const ulonglong2* row =
                reinterpret_cast<const ulonglong2*>(sxd2 + t * SDP);
            ulonglong2 x01 = row[0];
            ulonglong2 x23 = row[1];
            unsigned long long xv[PC] = {x01.x, x01.y, x23.x, x23.y};
            #pragma unroll
            for (int p = 0; p < PC; p++) {
                ai[p]  = fma2(xv[p], wip, ai[p]);
                ao[p]  = fma2(xv[p], wop, ao[p]);
                au[p]  = fma2(xv[p], wup, au[p]);
                axf[p] = fma2(xv[p], wfp, axf[p]);
            }
        }
        #pragma unroll 2
        for (int t = 0; t < M_; t++) {
            float ui = __ldg(Uiou + (size_t)t * G3_ + tid);
            float uo = __ldg(Uiou + (size_t)t * G3_ + M_ + tid);
            float uu = __ldg(Uiou + (size_t)t * G3_ + 2 * M_ + tid);
            float uf = __ldg(Uf   + (size_t)t * M_ + tid);
            unsigned long long uip = pack2(ui, ui);
            unsigned long long uop = pack2(uo, uo);
            unsigned long long uup = pack2(uu, uu);
            unsigned long long ufp = pack2(uf, uf);
            const ulonglong2* srow =
                reinterpret_cast<const ulonglong2*>(shs2 + t * SDP);
            ulonglong2 h01 = srow[0];
            ulonglong2 h23 = srow[1];
            unsigned long long hv[PC] = {h01.x, h01.y, h23.x, h23.y};
            #pragma unroll
            for (int p = 0; p < PC; p++) {
                ai[p] = fma2(hv[p], uip, ai[p]);
                ao[p] = fma2(hv[p], uop, ao[p]);
                au[p] = fma2(hv[p], uup, au[p]);
            }
            #pragma unroll
            for (int k = 0; k < K_; k++) {
                const ulonglong2* krow =
                    reinterpret_cast<const ulonglong2*>(sh2 + (k * M_ + t) * SHT);
                ulonglong2 k01 = krow[0];
                ulonglong2 k23 = krow[1];
                unsigned long long kv[PC] = {k01.x, k01.y, k23.x, k23.y};
                #pragma unroll
                for (int p = 0; p < PC; p++)
                    af[p][k] = fma2(kv[p], ufp, af[p][k]);
            }
        }

        const float bi = biou[tid], bo = biou[M_ + tid], bu = biou[2 * M_ + tid];
        const float bff = bf[tid];
        #pragma unroll
        for (int p = 0; p < PC; p++) {
            float i0, i1, o0, o1, u0, u1, x0, x1;
            unpack2(ai[p], i0, i1);
            unpack2(ao[p], o0, o1);
            unpack2(au[p], u0, u1);
            unpack2(axf[p], x0, x1);
            float f0[K_], f1[K_];
            #pragma unroll
            for (int k = 0; k < K_; k++) unpack2(af[p][k], f0[k], f1[k]);
            #pragma unroll
            for (int half = 0; half < 2; half++) {
                int l = 2 * p + half;
                if (styp[l] != 2) continue;
                int e = eb + l;
                float i_ = sigm((half ? i1 : i0) + bi);
                float o_ = sigm((half ? o1 : o0) + bo);
                float u_ = tanhf((half ? u1 : u0) + bu);
                float xf = half ? x1 : x0;
                float c  = i_ * u_;
                #pragma unroll
                for (int k = 0; k < K_; k++) {
                    int sl = sslot[l][k];
                    float f  = sigm(xf + (half ? f1[k] : f0[k]) + bff);
                    float cc = (sl >= 0) ? g_c[(size_t)sl * M_ + tid] : 0.0f;
                    c = fmaf(f, cc, c);
                }
                float h = o_ * tanhf(c);
                out[(size_t)e * M_ + tid] = c;
                out[(size_t)NCTX * M_ + (size_t)e * M_ + tid] = h;
            }
        }
    }
}

// ---------------------------------------------------------------------------
// Kernel D: leaf-type and zero-type ctx elements
// ---------------------------------------------------------------------------
__global__ void finish_kernel(float* __restrict__ out) {
    int idx = blockIdx.x * blockDim.x + threadIdx.x;
    if (idx >= NCTX * M_) return;
    int e = idx / M_;
    int m = idx - e * M_;
    int t = g_type[e];
    if (t == 2) return;
    float c = 0.f, h = 0.f;
    if (t == 1) {
        int sl = g_slot[e * 5];
        if (sl >= 0) {
            c = g_c[(size_t)sl * M_ + m];
            h = g_h[(size_t)sl * M_ + m];
        }
    }
    out[idx] = c;
    out[(size_t)NCTX * M_ + idx] = h;
}

// ---------------------------------------------------------------------------
extern "C" void kernel_launch(void* const* d_in, const int* in_sizes, int n_in,
                              void* d_out, int out_size) {
    const float* embed     = (const float*)d_in[0];
    const float* W_leaf    = (const float*)d_in[1];
    const float* b_leaf    = (const float*)d_in[2];
    const float* W_iou     = (const float*)d_in[3];
    const float* U_iou     = (const float*)d_in[4];
    const float* b_iou     = (const float*)d_in[5];
    const float* W_f       = (const float*)d_in[6];
    const float* U_f       = (const float*)d_in[7];
    const float* b_f       = (const float*)d_in[8];
    const int*   leaf_idx  = (const int*)d_in[9];
    const int*   dep_word  = (const int*)d_in[10];
    const int*   dep_child = (const int*)d_in[11];
    const int*   ctx_idx   = (const int*)d_in[12];
    float* out = (float*)d_out;

    cudaFuncSetAttribute(leaf_gemm_kernel,
                         cudaFuncAttributeMaxDynamicSharedMemorySize, SMEM_GEMM);

    init_kernel<<<1, 32>>>();
    build_jobs_kernel<<<(NCTX + 255) / 256, 256>>>(ctx_idx, dep_word, dep_child, leaf_idx);
    prep_w_frag_kernel<<<(KCH * NT * 32 + 255) / 256, 256>>>(W_leaf);
    prep_x_frag_kernel<<<(NMT * KCH * 32 + 255) / 256, 256>>>(embed);
    leaf_gemm_kernel<<<NJOB / 32, 256, SMEM_GEMM>>>(b_leaf);
    dep_kernel<<<NCTX / TC, 160>>>(embed, W_iou, U_iou, b_iou, W_f, U_f, b_f, out);
    finish_kernel<<<(NCTX * M_ + 255) / 256, 256>>>(out);
}